// round 14
// baseline (speedup 1.0000x reference)
#include <cuda_runtime.h>
#include <math.h>
#include <float.h>

#define BB 32
#define TT 64
#define VV 40000
#define NB 49
#define WIN 7
#define GH 200
#define GW 200
#define EPS_INV 10.0f
#define SINK_ITERS 3
#define NUM_N 5
#define LOG2E 1.4426950408889634f

__device__ float g_U[BB * TT * TT];

// ---------------------------------------------------------------------------
// One block per (b,i) row. Phase A gathers neighbor logits into smem (frees
// registers for the stream). Phase B is a software-pipelined stream: chunk
// i+1's loads issue before chunk i is consumed, so the memory pipe never
// drains. Phase C finishes the gather from smem.
__global__ void __launch_bounds__(256, 2) softmax_u_kernel(
        const float* __restrict__ logits,
        const int*   __restrict__ tgt,
        const float* __restrict__ kernel_w,
        const int*   __restrict__ nb_ids,
        float*       __restrict__ out) {
    const int row = blockIdx.x;           // b*TT + i
    const int b = row >> 6;
    const float* __restrict__ L = logits + (size_t)row * VV;
    const int tid = threadIdx.x;
    const int lane = tid & 31;
    const int wid = tid >> 5;

    if (row == 0 && tid == 0) out[0] = 0.0f;

    __shared__ float kwsh[64];
    __shared__ int   tgtsh[64];
    __shared__ float gath[64][64];        // gathered logits [j][k]
    __shared__ float smS[8], smZ;

    if (tid < 64) {
        kwsh[tid]  = (tid < NB) ? kernel_w[tid] : 0.0f;
        tgtsh[tid] = tgt[b * TT + tid];
    }
    __syncthreads();

    // -------- Phase A: gather neighbor logits into smem --------------------
    // Warp wid handles j = wid, wid+8, ... Lane L fills gath[j][L] and
    // gath[j][L+32]; the same lane reads them back in phase C (no sync).
    const bool k1ok = (lane < NB);
    const bool k2ok = (lane + 32 < NB);
#pragma unroll
    for (int jj = 0; jj < 8; jj++) {
        int j = wid + jj * 8;
        int t = tgtsh[j];
        if (k1ok) gath[j][lane]      = L[nb_ids[t * NB + lane]];
        if (k2ok) gath[j][lane + 32] = L[nb_ids[t * NB + lane + 32]];
    }

    // -------- Phase B: pipelined streaming sum of exp ----------------------
    float s0 = 0.0f, s1 = 0.0f, s2 = 0.0f, s3 = 0.0f;
    const float4* __restrict__ L4 = (const float4*)L;   // 10000 float4s

    float4 c0 = L4[tid];
    float4 c1 = L4[tid + 256];
    float4 c2 = L4[tid + 512];
    float4 c3 = L4[tid + 768];
    int base = tid + 1024;
#pragma unroll 1
    for (int it = 0; it < 8; it++, base += 1024) {
        float4 n0 = L4[base];
        float4 n1 = L4[base + 256];
        float4 n2 = L4[base + 512];
        float4 n3 = L4[base + 768];
        s0 += exp2f(c0.x * LOG2E); s1 += exp2f(c0.y * LOG2E);
        s2 += exp2f(c0.z * LOG2E); s3 += exp2f(c0.w * LOG2E);
        s0 += exp2f(c1.x * LOG2E); s1 += exp2f(c1.y * LOG2E);
        s2 += exp2f(c1.z * LOG2E); s3 += exp2f(c1.w * LOG2E);
        s0 += exp2f(c2.x * LOG2E); s1 += exp2f(c2.y * LOG2E);
        s2 += exp2f(c2.z * LOG2E); s3 += exp2f(c2.w * LOG2E);
        s0 += exp2f(c3.x * LOG2E); s1 += exp2f(c3.y * LOG2E);
        s2 += exp2f(c3.z * LOG2E); s3 += exp2f(c3.w * LOG2E);
        c0 = n0; c1 = n1; c2 = n2; c3 = n3;
    }
    // epilogue: last full chunk (loaded in final loop iteration)
    s0 += exp2f(c0.x * LOG2E); s1 += exp2f(c0.y * LOG2E);
    s2 += exp2f(c0.z * LOG2E); s3 += exp2f(c0.w * LOG2E);
    s0 += exp2f(c1.x * LOG2E); s1 += exp2f(c1.y * LOG2E);
    s2 += exp2f(c1.z * LOG2E); s3 += exp2f(c1.w * LOG2E);
    s0 += exp2f(c2.x * LOG2E); s1 += exp2f(c2.y * LOG2E);
    s2 += exp2f(c2.z * LOG2E); s3 += exp2f(c2.w * LOG2E);
    s0 += exp2f(c3.x * LOG2E); s1 += exp2f(c3.y * LOG2E);
    s2 += exp2f(c3.z * LOG2E); s3 += exp2f(c3.w * LOG2E);
    // remainder: float4s 9216..9999
    for (int i = 9216 + tid; i < VV / 4; i += 256) {
        float4 v = L4[i];
        s0 += exp2f(v.x * LOG2E); s1 += exp2f(v.y * LOG2E);
        s2 += exp2f(v.z * LOG2E); s3 += exp2f(v.w * LOG2E);
    }

    float s = (s0 + s1) + (s2 + s3);
#pragma unroll
    for (int o = 16; o > 0; o >>= 1)
        s += __shfl_down_sync(0xffffffffu, s, o);
    if (lane == 0) smS[wid] = s;
    __syncthreads();
    if (tid == 0) {
        float tot = 0.0f;
#pragma unroll
        for (int w = 0; w < 8; w++) tot += smS[w];
        smZ = 1.0f / tot;
    }
    __syncthreads();
    const float zinv = smZ;

    // -------- Phase C: finish gathers from smem, write U row ---------------
    const int k2 = lane + 32;
#pragma unroll
    for (int jj = 0; jj < 8; jj++) {
        int j = wid + jj * 8;
        int t = tgtsh[j];
        int rr = t / GW, cc = t - rr * GW;
        float e = 0.0f, w = 0.0f;
        if (k1ok) {
            int dy = lane / WIN - 3;
            int dx = lane - (lane / WIN) * WIN - 3;
            int rn = rr + dy, cn = cc + dx;
            bool valid = (rn >= 0) && (rn < GH) && (cn >= 0) && (cn < GW);
            float wk = valid ? kwsh[lane] : 0.0f;
            e = exp2f(gath[j][lane] * LOG2E) * wk;
            w = wk;
        }
        if (k2ok) {
            int dy = k2 / WIN - 3;
            int dx = k2 - (k2 / WIN) * WIN - 3;
            int rn = rr + dy, cn = cc + dx;
            bool valid = (rn >= 0) && (rn < GH) && (cn >= 0) && (cn < GW);
            float wk = valid ? kwsh[k2] : 0.0f;
            e += exp2f(gath[j][k2] * LOG2E) * wk;
            w += wk;
        }
#pragma unroll
        for (int o = 16; o > 0; o >>= 1) {
            e += __shfl_down_sync(0xffffffffu, e, o);
            w += __shfl_down_sync(0xffffffffu, w, o);
        }
        if (lane == 0)
            g_U[row * TT + j] = fmaxf(__fdividef(e, fmaxf(w, 1e-12f)) * zinv, 1e-12f);
    }
}

// ---------------------------------------------------------------------------
// Sinkhorn (frozen: all variants measure ~10us; latency-bound setup).
// U staged in smem; S row/col slices computed directly into registers.
template<int NIDX>
__device__ __forceinline__ void sinkhorn_impl(
        float* Ush, float* av, float* bv, float* red,
        const float* __restrict__ weights, float* __restrict__ out) {
    constexpr int n = NIDX + 1;
    constexpr int I = TT - n + 1;
    constexpr int UST = 68;
    const int b = blockIdx.x;
    const int tid = threadIdx.x;          // 0..255

    const float4* __restrict__ U4 = (const float4*)(g_U + b * TT * TT);
#pragma unroll
    for (int v = 0; v < 4; v++) {
        int i = tid + v * 256;
        int r = i >> 4, c4 = i & 15;
        *(float4*)&Ush[r * UST + c4 * 4] = U4[i];
    }
    if (tid < 64) { av[tid] = 1.0f; bv[tid] = 1.0f; }
    __syncthreads();

    const int r = tid >> 2;
    const int part = tid & 3;
    const int j0 = part * 16;
    const bool rv = (r < I);

    float Sreg[16], Kreg[16], KTreg[16];
#pragma unroll
    for (int t = 0; t < 16; t++) {
        int j = j0 + t;
        bool ok = rv && (j < I);
        int rs = ok ? r : 0;
        int js = ok ? j : 0;
        float pr = Ush[rs * UST + js];
        float pc = Ush[js * UST + rs];
#pragma unroll
        for (int k = 1; k < n; k++) {
            pr *= Ush[(rs + k) * UST + js + k];
            pc *= Ush[(js + k) * UST + rs + k];
        }
        float sr = fmaxf(pr, 1e-12f);
        float sc = fmaxf(pc, 1e-12f);
        Sreg[t] = ok ? sr : 0.0f;
        float xr = sr * EPS_INV;
        float er = fmaf(xr, 0.166666667f, 0.5f);
        er = fmaf(xr, er, 1.0f);
        Kreg[t] = ok ? fmaf(xr, er, 1.0f) : 0.0f;
        float xc = sc * EPS_INV;
        float ec = fmaf(xc, 0.166666667f, 0.5f);
        ec = fmaf(xc, ec, 1.0f);
        KTreg[t] = ok ? fmaf(xc, ec, 1.0f) : 0.0f;
    }

    constexpr float mu = 1.0f / (float)I;

#pragma unroll 1
    for (int it = 0; it < SINK_ITERS; it++) {
        {
            float a0 = 0, a1 = 0, a2 = 0, a3 = 0;
#pragma unroll
            for (int t = 0; t < 16; t += 4) {
                a0 += Kreg[t]     * bv[j0 + t];
                a1 += Kreg[t + 1] * bv[j0 + t + 1];
                a2 += Kreg[t + 2] * bv[j0 + t + 2];
                a3 += Kreg[t + 3] * bv[j0 + t + 3];
            }
            float sum = (a0 + a1) + (a2 + a3);
            sum += __shfl_down_sync(0xffffffffu, sum, 2);
            sum += __shfl_down_sync(0xffffffffu, sum, 1);
            if (part == 0 && rv)
                av[r] = __fdividef(mu, fmaxf(sum, 1e-30f));
        }
        __syncthreads();
        {
            float a0 = 0, a1 = 0, a2 = 0, a3 = 0;
#pragma unroll
            for (int t = 0; t < 16; t += 4) {
                a0 += KTreg[t]     * av[j0 + t];
                a1 += KTreg[t + 1] * av[j0 + t + 1];
                a2 += KTreg[t + 2] * av[j0 + t + 2];
                a3 += KTreg[t + 3] * av[j0 + t + 3];
            }
            float sum = (a0 + a1) + (a2 + a3);
            sum += __shfl_down_sync(0xffffffffu, sum, 2);
            sum += __shfl_down_sync(0xffffffffu, sum, 1);
            if (part == 0 && rv)
                bv[r] = __fdividef(mu, fmaxf(sum, 1e-30f));
        }
        __syncthreads();
    }

    float pq = 0.0f;
#pragma unroll
    for (int t = 0; t < 16; t++)
        pq += Kreg[t] * bv[j0 + t] * Sreg[t];
    float q = rv ? av[r] * pq : 0.0f;
#pragma unroll
    for (int o = 16; o > 0; o >>= 1)
        q += __shfl_down_sync(0xffffffffu, q, o);
    const int wid = tid >> 5, lane = tid & 31;
    if (lane == 0) red[wid] = q;
    __syncthreads();
    if (tid == 0) {
        float tot = ((red[0] + red[1]) + (red[2] + red[3]))
                  + ((red[4] + red[5]) + (red[6] + red[7]));
        tot = fmaxf(tot, 1e-12f);
        atomicAdd(out, -weights[NIDX] * logf(tot) * (1.0f / (float)BB));
    }
}

__global__ void __launch_bounds__(256, 2) sinkhorn_kernel(
        const float* __restrict__ weights, float* __restrict__ out) {
    __shared__ float Ush[64 * 68];
    __shared__ float av[64], bv[64], red[8];
    switch (blockIdx.y) {
        case 0: sinkhorn_impl<0>(Ush, av, bv, red, weights, out); break;
        case 1: sinkhorn_impl<1>(Ush, av, bv, red, weights, out); break;
        case 2: sinkhorn_impl<2>(Ush, av, bv, red, weights, out); break;
        case 3: sinkhorn_impl<3>(Ush, av, bv, red, weights, out); break;
        default: sinkhorn_impl<4>(Ush, av, bv, red, weights, out); break;
    }
}

// ---------------------------------------------------------------------------
extern "C" void kernel_launch(void* const* d_in, const int* in_sizes, int n_in,
                              void* d_out, int out_size) {
    const float* logits   = (const float*)d_in[0];
    const int*   tgt      = (const int*)  d_in[1];
    const float* kernel_w = (const float*)d_in[2];
    const int*   nb_ids   = (const int*)  d_in[3];
    const float* weights  = (const float*)d_in[5];
    float* out = (float*)d_out;

    softmax_u_kernel<<<BB * TT, 256>>>(logits, tgt, kernel_w, nb_ids, out);
    sinkhorn_kernel<<<dim3(BB, NUM_N), 256>>>(weights, out);
}

// round 15
// speedup vs baseline: 1.1308x; 1.1308x over previous
#include <cuda_runtime.h>
#include <math.h>
#include <float.h>

#define BB 32
#define TT 64
#define VV 40000
#define NB 49
#define WIN 7
#define GH 200
#define GW 200
#define EPS_INV 10.0f
#define SINK_ITERS 3
#define NUM_N 5
#define LOG2E 1.4426950408889634f

__device__ float g_U[BB * TT * TT];

// ---------------------------------------------------------------------------
// One block per (b,i) row. Register gather issued first, 8-deep float4
// streaming while gathers are in flight (measured best config, R6: ~63us),
// gather finish at the end.
__global__ void __launch_bounds__(256) softmax_u_kernel(
        const float* __restrict__ logits,
        const int*   __restrict__ tgt,
        const float* __restrict__ kernel_w,
        const int*   __restrict__ nb_ids,
        float*       __restrict__ out) {
    const int row = blockIdx.x;           // b*TT + i
    const int b = row >> 6;
    const float* __restrict__ L = logits + (size_t)row * VV;
    const int tid = threadIdx.x;
    const int lane = tid & 31;
    const int wid = tid >> 5;

    if (row == 0 && tid == 0) out[0] = 0.0f;

    __shared__ float kwsh[64];
    __shared__ int   tgtsh[64];
    __shared__ float smS[8], smZ;

    if (tid < 64) {
        kwsh[tid]  = (tid < NB) ? kernel_w[tid] : 0.0f;
        tgtsh[tid] = tgt[b * TT + tid];
    }
    __syncthreads();

    // -------- Phase A: issue gather loads (warp per j, 8 j's per warp) ----
    const bool k1ok = (lane < NB);
    const bool k2ok = (lane + 32 < NB);
    int   tloc[8];
    float la[8], lb[8];
#pragma unroll
    for (int jj = 0; jj < 8; jj++) {
        int j = wid + jj * 8;
        int t = tgtsh[j];
        tloc[jj] = t;
        int n1 = k1ok ? nb_ids[t * NB + lane]      : 0;
        int n2 = k2ok ? nb_ids[t * NB + lane + 32] : 0;
        la[jj] = L[n1];
        lb[jj] = L[n2];
    }

    // -------- Phase B: streaming sum of exp (8 float4 in flight) ----------
    float s0 = 0.0f, s1 = 0.0f, s2 = 0.0f, s3 = 0.0f;
    const float4* __restrict__ L4 = (const float4*)L;   // 10000 float4s
    int base = tid;
#pragma unroll 1
    for (int it = 0; it < 4; it++, base += 2048) {      // 4*2048 = 8192
        float4 v0 = L4[base];
        float4 v1 = L4[base + 256];
        float4 v2 = L4[base + 512];
        float4 v3 = L4[base + 768];
        float4 v4 = L4[base + 1024];
        float4 v5 = L4[base + 1280];
        float4 v6 = L4[base + 1536];
        float4 v7 = L4[base + 1792];
        s0 += exp2f(v0.x * LOG2E); s1 += exp2f(v0.y * LOG2E);
        s2 += exp2f(v0.z * LOG2E); s3 += exp2f(v0.w * LOG2E);
        s0 += exp2f(v1.x * LOG2E); s1 += exp2f(v1.y * LOG2E);
        s2 += exp2f(v1.z * LOG2E); s3 += exp2f(v1.w * LOG2E);
        s0 += exp2f(v2.x * LOG2E); s1 += exp2f(v2.y * LOG2E);
        s2 += exp2f(v2.z * LOG2E); s3 += exp2f(v2.w * LOG2E);
        s0 += exp2f(v3.x * LOG2E); s1 += exp2f(v3.y * LOG2E);
        s2 += exp2f(v3.z * LOG2E); s3 += exp2f(v3.w * LOG2E);
        s0 += exp2f(v4.x * LOG2E); s1 += exp2f(v4.y * LOG2E);
        s2 += exp2f(v4.z * LOG2E); s3 += exp2f(v4.w * LOG2E);
        s0 += exp2f(v5.x * LOG2E); s1 += exp2f(v5.y * LOG2E);
        s2 += exp2f(v5.z * LOG2E); s3 += exp2f(v5.w * LOG2E);
        s0 += exp2f(v6.x * LOG2E); s1 += exp2f(v6.y * LOG2E);
        s2 += exp2f(v6.z * LOG2E); s3 += exp2f(v6.w * LOG2E);
        s0 += exp2f(v7.x * LOG2E); s1 += exp2f(v7.y * LOG2E);
        s2 += exp2f(v7.z * LOG2E); s3 += exp2f(v7.w * LOG2E);
    }
    // remainder: 10000 - 8192 = 1808 float4s
#pragma unroll 1
    for (int i = 8192 + tid; i < VV / 4; i += 256) {
        float4 v = L4[i];
        s0 += exp2f(v.x * LOG2E); s1 += exp2f(v.y * LOG2E);
        s2 += exp2f(v.z * LOG2E); s3 += exp2f(v.w * LOG2E);
    }

    float s = (s0 + s1) + (s2 + s3);
#pragma unroll
    for (int o = 16; o > 0; o >>= 1)
        s += __shfl_down_sync(0xffffffffu, s, o);
    if (lane == 0) smS[wid] = s;
    __syncthreads();
    if (tid == 0) {
        float tot = 0.0f;
#pragma unroll
        for (int w = 0; w < 8; w++) tot += smS[w];
        smZ = 1.0f / tot;
    }
    __syncthreads();
    const float zinv = smZ;

    // -------- Phase C: finish gathers, write U row ------------------------
    const int k2 = lane + 32;
#pragma unroll
    for (int jj = 0; jj < 8; jj++) {
        int j = wid + jj * 8;
        int t = tloc[jj];
        int rr = t / GW, cc = t - rr * GW;
        float e = 0.0f, w = 0.0f;
        if (k1ok) {
            int dy = lane / WIN - 3;
            int dx = lane - (lane / WIN) * WIN - 3;
            int rn = rr + dy, cn = cc + dx;
            bool valid = (rn >= 0) && (rn < GH) && (cn >= 0) && (cn < GW);
            float wk = valid ? kwsh[lane] : 0.0f;
            e = exp2f(la[jj] * LOG2E) * wk;
            w = wk;
        }
        if (k2ok) {
            int dy = k2 / WIN - 3;
            int dx = k2 - (k2 / WIN) * WIN - 3;
            int rn = rr + dy, cn = cc + dx;
            bool valid = (rn >= 0) && (rn < GH) && (cn >= 0) && (cn < GW);
            float wk = valid ? kwsh[k2] : 0.0f;
            e += exp2f(lb[jj] * LOG2E) * wk;
            w += wk;
        }
#pragma unroll
        for (int o = 16; o > 0; o >>= 1) {
            e += __shfl_down_sync(0xffffffffu, e, o);
            w += __shfl_down_sync(0xffffffffu, w, o);
        }
        if (lane == 0)
            g_U[row * TT + j] = fmaxf(__fdividef(e, fmaxf(w, 1e-12f)) * zinv, 1e-12f);
    }
}

// ---------------------------------------------------------------------------
// Sinkhorn (frozen at measured best, R14: 9.66us). U staged in smem;
// S row/col slices computed directly into registers; poly exp; 3 iters.
template<int NIDX>
__device__ __forceinline__ void sinkhorn_impl(
        float* Ush, float* av, float* bv, float* red,
        const float* __restrict__ weights, float* __restrict__ out) {
    constexpr int n = NIDX + 1;
    constexpr int I = TT - n + 1;
    constexpr int UST = 68;
    const int b = blockIdx.x;
    const int tid = threadIdx.x;          // 0..255

    const float4* __restrict__ U4 = (const float4*)(g_U + b * TT * TT);
#pragma unroll
    for (int v = 0; v < 4; v++) {
        int i = tid + v * 256;
        int r = i >> 4, c4 = i & 15;
        *(float4*)&Ush[r * UST + c4 * 4] = U4[i];
    }
    if (tid < 64) { av[tid] = 1.0f; bv[tid] = 1.0f; }
    __syncthreads();

    const int r = tid >> 2;
    const int part = tid & 3;
    const int j0 = part * 16;
    const bool rv = (r < I);

    float Sreg[16], Kreg[16], KTreg[16];
#pragma unroll
    for (int t = 0; t < 16; t++) {
        int j = j0 + t;
        bool ok = rv && (j < I);
        int rs = ok ? r : 0;
        int js = ok ? j : 0;
        float pr = Ush[rs * UST + js];
        float pc = Ush[js * UST + rs];
#pragma unroll
        for (int k = 1; k < n; k++) {
            pr *= Ush[(rs + k) * UST + js + k];
            pc *= Ush[(js + k) * UST + rs + k];
        }
        float sr = fmaxf(pr, 1e-12f);
        float sc = fmaxf(pc, 1e-12f);
        Sreg[t] = ok ? sr : 0.0f;
        float xr = sr * EPS_INV;
        float er = fmaf(xr, 0.166666667f, 0.5f);
        er = fmaf(xr, er, 1.0f);
        Kreg[t] = ok ? fmaf(xr, er, 1.0f) : 0.0f;
        float xc = sc * EPS_INV;
        float ec = fmaf(xc, 0.166666667f, 0.5f);
        ec = fmaf(xc, ec, 1.0f);
        KTreg[t] = ok ? fmaf(xc, ec, 1.0f) : 0.0f;
    }

    constexpr float mu = 1.0f / (float)I;

#pragma unroll 1
    for (int it = 0; it < SINK_ITERS; it++) {
        {
            float a0 = 0, a1 = 0, a2 = 0, a3 = 0;
#pragma unroll
            for (int t = 0; t < 16; t += 4) {
                a0 += Kreg[t]     * bv[j0 + t];
                a1 += Kreg[t + 1] * bv[j0 + t + 1];
                a2 += Kreg[t + 2] * bv[j0 + t + 2];
                a3 += Kreg[t + 3] * bv[j0 + t + 3];
            }
            float sum = (a0 + a1) + (a2 + a3);
            sum += __shfl_down_sync(0xffffffffu, sum, 2);
            sum += __shfl_down_sync(0xffffffffu, sum, 1);
            if (part == 0 && rv)
                av[r] = __fdividef(mu, fmaxf(sum, 1e-30f));
        }
        __syncthreads();
        {
            float a0 = 0, a1 = 0, a2 = 0, a3 = 0;
#pragma unroll
            for (int t = 0; t < 16; t += 4) {
                a0 += KTreg[t]     * av[j0 + t];
                a1 += KTreg[t + 1] * av[j0 + t + 1];
                a2 += KTreg[t + 2] * av[j0 + t + 2];
                a3 += KTreg[t + 3] * av[j0 + t + 3];
            }
            float sum = (a0 + a1) + (a2 + a3);
            sum += __shfl_down_sync(0xffffffffu, sum, 2);
            sum += __shfl_down_sync(0xffffffffu, sum, 1);
            if (part == 0 && rv)
                bv[r] = __fdividef(mu, fmaxf(sum, 1e-30f));
        }
        __syncthreads();
    }

    float pq = 0.0f;
#pragma unroll
    for (int t = 0; t < 16; t++)
        pq += Kreg[t] * bv[j0 + t] * Sreg[t];
    float q = rv ? av[r] * pq : 0.0f;
#pragma unroll
    for (int o = 16; o > 0; o >>= 1)
        q += __shfl_down_sync(0xffffffffu, q, o);
    const int wid = tid >> 5, lane = tid & 31;
    if (lane == 0) red[wid] = q;
    __syncthreads();
    if (tid == 0) {
        float tot = ((red[0] + red[1]) + (red[2] + red[3]))
                  + ((red[4] + red[5]) + (red[6] + red[7]));
        tot = fmaxf(tot, 1e-12f);
        atomicAdd(out, -weights[NIDX] * logf(tot) * (1.0f / (float)BB));
    }
}

__global__ void __launch_bounds__(256, 2) sinkhorn_kernel(
        const float* __restrict__ weights, float* __restrict__ out) {
    __shared__ float Ush[64 * 68];
    __shared__ float av[64], bv[64], red[8];
    switch (blockIdx.y) {
        case 0: sinkhorn_impl<0>(Ush, av, bv, red, weights, out); break;
        case 1: sinkhorn_impl<1>(Ush, av, bv, red, weights, out); break;
        case 2: sinkhorn_impl<2>(Ush, av, bv, red, weights, out); break;
        case 3: sinkhorn_impl<3>(Ush, av, bv, red, weights, out); break;
        default: sinkhorn_impl<4>(Ush, av, bv, red, weights, out); break;
    }
}

// ---------------------------------------------------------------------------
extern "C" void kernel_launch(void* const* d_in, const int* in_sizes, int n_in,
                              void* d_out, int out_size) {
    const float* logits   = (const float*)d_in[0];
    const int*   tgt      = (const int*)  d_in[1];
    const float* kernel_w = (const float*)d_in[2];
    const int*   nb_ids   = (const int*)  d_in[3];
    const float* weights  = (const float*)d_in[5];
    float* out = (float*)d_out;

    softmax_u_kernel<<<BB * TT, 256>>>(logits, tgt, kernel_w, nb_ids, out);
    sinkhorn_kernel<<<dim3(BB, NUM_N), 256>>>(weights, out);
}